// round 13
// baseline (speedup 1.0000x reference)
#include <cuda_runtime.h>
#include <math.h>

#define NB 8
#define NC 256
#define NHW 1024
#define NHEAD 8
#define NHD 32
#define NN 102
#define NGD 64

// ---------------- static device scratch ----------------
static __device__ float d_xs[NB*NHW*NC];          // x transposed: [B, HW, C]
static __device__ int   d_nodeof[NB*NHW];         // hw -> node index or -1
static __device__ float d_feats[NB*NN*NC];        // raw node features
static __device__ float d_fn[NB*NN*NC];           // row-normalized node features
static __device__ unsigned char d_adj[NB*NN*NN];
static __device__ float d_h[NB*NN*NGD];           // GAT pre-aggregation features
static __device__ float d_asrc[NB*NN];
static __device__ float d_adst[NB*NN];
static __device__ float d_g0[NB*NN*NGD];
static __device__ float d_g1[NB*NN*NGD];
static __device__ float d_gh[NB*NHEAD*NHW];       // per-(b,h,hw) gate (0 if not a node)
static __device__ float d_q[NB*NHEAD*NHW*NHD];
static __device__ float d_k[NB*NHEAD*NHW*NHD];
static __device__ float d_v[NB*NHEAD*NHW*NHD];
static __device__ float d_ao[NB*NHW*NC];          // attention output [B, HW, C]

__device__ __forceinline__ float wsum(float v){
  #pragma unroll
  for (int o = 16; o; o >>= 1) v += __shfl_xor_sync(0xffffffffu, v, o);
  return v;
}
__device__ __forceinline__ unsigned f2tf32(float f){
  unsigned r; asm("cvt.rna.tf32.f32 %0, %1;" : "=r"(r) : "f"(f)); return r;
}
__device__ __forceinline__ uint4 cvt4(float4 v){
  return make_uint4(f2tf32(v.x), f2tf32(v.y), f2tf32(v.z), f2tf32(v.w));
}
__device__ __forceinline__ void mma_tf32(float* d, const unsigned* a, unsigned b0, unsigned b1){
  asm volatile("mma.sync.aligned.m16n8k8.row.col.f32.tf32.tf32.f32 "
    "{%0,%1,%2,%3}, {%4,%5,%6,%7}, {%8,%9}, {%0,%1,%2,%3};\n"
    : "+f"(d[0]), "+f"(d[1]), "+f"(d[2]), "+f"(d[3])
    : "r"(a[0]), "r"(a[1]), "r"(a[2]), "r"(a[3]), "r"(b0), "r"(b1));
}

// ---------------- 1) transpose x [B,C,HW] -> xs [B,HW,C] ----------------
__global__ void transpose_kernel(const float* __restrict__ x){
  __shared__ float tile[32][33];
  int b = blockIdx.z;
  int hw0 = blockIdx.x * 32, c0 = blockIdx.y * 32;
  int tx = threadIdx.x, ty = threadIdx.y;
  #pragma unroll
  for (int i = 0; i < 4; i++)
    tile[ty + 8*i][tx] = x[((size_t)b*NC + (c0 + ty + 8*i))*NHW + hw0 + tx];
  __syncthreads();
  #pragma unroll
  for (int i = 0; i < 4; i++)
    d_xs[((size_t)b*NHW + (hw0 + ty + 8*i))*NC + c0 + tx] = tile[tx][ty + 8*i];
}

// ---- 2+3+4) variance + top-102 bitonic + gather + normalize (fused, block=batch) ----
__global__ __launch_bounds__(1024) void imptopk_kernel(){
  __shared__ float key[1024];
  __shared__ int   idxv[1024];
  __shared__ int   tops[NN];
  __shared__ float rinv[NN];
  int b = blockIdx.x, tid = threadIdx.x;
  int w = tid >> 5, lane = tid & 31;
  // variance phase: warp-per-row, 32 rounds
  for (int r = 0; r < 32; r++){
    int row = r*32 + w;
    const float* p = d_xs + ((size_t)b*NHW + row)*NC;
    float v[8]; float s = 0.f;
    #pragma unroll
    for (int i = 0; i < 8; i++){ v[i] = p[lane + 32*i]; s += v[i]; }
    s = wsum(s);
    float mean = s * (1.f/256.f);
    float q = 0.f;
    #pragma unroll
    for (int i = 0; i < 8; i++){ float d = v[i] - mean; q += d*d; }
    q = wsum(q);
    if (lane == 0) key[row] = q * (1.f/255.f);
  }
  idxv[tid] = tid;
  d_nodeof[b*NHW + tid] = -1;
  __syncthreads();
  for (int k = 2; k <= 1024; k <<= 1){
    for (int j = k >> 1; j > 0; j >>= 1){
      int ixj = tid ^ j;
      if (ixj > tid){
        bool desc = ((tid & k) == 0);
        float a = key[tid], bb = key[ixj];
        if (desc ? (a < bb) : (a > bb)){
          key[tid] = bb; key[ixj] = a;
          int t = idxv[tid]; idxv[tid] = idxv[ixj]; idxv[ixj] = t;
        }
      }
      __syncthreads();
    }
  }
  if (tid < NN){
    int src = idxv[tid];
    tops[tid] = src;
    d_nodeof[b*NHW + src] = tid;
  }
  __syncthreads();
  // gather raw features
  for (int idx = tid; idx < NN*NC; idx += 1024){
    int i = idx >> 8, c = idx & 255;
    d_feats[((size_t)b*NN + i)*NC + c] = d_xs[((size_t)b*NHW + tops[i])*NC + c];
  }
  __syncthreads();
  // row norms (warp per node)
  for (int i = w; i < NN; i += 32){
    const float* p = d_feats + ((size_t)b*NN + i)*NC;
    float s = 0.f;
    #pragma unroll
    for (int k = 0; k < 8; k++){ float v = p[lane + 32*k]; s += v*v; }
    s = wsum(s);
    if (lane == 0) rinv[i] = 1.f / fmaxf(sqrtf(s), 1e-12f);
  }
  __syncthreads();
  // normalized features
  for (int idx = tid; idx < NN*NC; idx += 1024){
    int i = idx >> 8, c = idx & 255;
    d_fn[((size_t)b*NN + i)*NC + c] = d_feats[((size_t)b*NN + i)*NC + c] * rinv[i];
  }
}

// ---------------- 6) adjacency via 3x-tf32 mma: SIM = Fn Fn^T > 0.6 (+self) ----------------
__global__ __launch_bounds__(256) void adj_mma(){
  __shared__ unsigned Ah[128*20];
  __shared__ unsigned Al[128*20];
  int b = blockIdx.x;
  int tid = threadIdx.x, w = tid>>5, lane = tid&31;
  int g = lane>>2, t = lane&3;
  int mo = (w>>1)*32, no = (w&1)*64;
  float acc[2][8][4];
  #pragma unroll
  for (int mt=0;mt<2;mt++)
    #pragma unroll
    for (int nt=0;nt<8;nt++)
      #pragma unroll
      for (int r=0;r<4;r++) acc[mt][nt][r] = 0.f;

  const float* Fb = d_fn + (size_t)b*NN*NC;
  for (int k0 = 0; k0 < 256; k0 += 16){
    __syncthreads();
    #pragma unroll
    for (int l = 0; l < 2; l++){
      int idx = tid + l*256;
      int r = idx>>2, c4 = (idx&3)<<2;
      float4 va = (r < NN) ? *(const float4*)&Fb[(size_t)r*NC + k0 + c4]
                           : make_float4(0.f,0.f,0.f,0.f);
      unsigned hx = f2tf32(va.x), hy = f2tf32(va.y), hz = f2tf32(va.z), hw4 = f2tf32(va.w);
      *(uint4*)&Ah[r*20 + c4] = make_uint4(hx, hy, hz, hw4);
      *(uint4*)&Al[r*20 + c4] = make_uint4(
          f2tf32(va.x - __uint_as_float(hx)),
          f2tf32(va.y - __uint_as_float(hy)),
          f2tf32(va.z - __uint_as_float(hz)),
          f2tf32(va.w - __uint_as_float(hw4)));
    }
    __syncthreads();
    #pragma unroll
    for (int kc = 0; kc < 2; kc++){
      unsigned ah[2][4], al[2][4];
      #pragma unroll
      for (int mt = 0; mt < 2; mt++){
        int r = mo + mt*16;
        ah[mt][0] = Ah[(r+g  )*20 + kc*8 + t];
        ah[mt][1] = Ah[(r+g+8)*20 + kc*8 + t];
        ah[mt][2] = Ah[(r+g  )*20 + kc*8 + t + 4];
        ah[mt][3] = Ah[(r+g+8)*20 + kc*8 + t + 4];
        al[mt][0] = Al[(r+g  )*20 + kc*8 + t];
        al[mt][1] = Al[(r+g+8)*20 + kc*8 + t];
        al[mt][2] = Al[(r+g  )*20 + kc*8 + t + 4];
        al[mt][3] = Al[(r+g+8)*20 + kc*8 + t + 4];
      }
      #pragma unroll
      for (int nt = 0; nt < 8; nt++){
        int br = (no + nt*8 + g)*20 + kc*8 + t;
        unsigned b0h = Ah[br], b1h = Ah[br+4];
        unsigned b0l = Al[br], b1l = Al[br+4];
        mma_tf32(acc[0][nt], ah[0], b0h, b1h);
        mma_tf32(acc[0][nt], ah[0], b0l, b1l);
        mma_tf32(acc[0][nt], al[0], b0h, b1h);
        mma_tf32(acc[1][nt], ah[1], b0h, b1h);
        mma_tf32(acc[1][nt], ah[1], b0l, b1l);
        mma_tf32(acc[1][nt], al[1], b0h, b1h);
      }
    }
  }
  unsigned char* adjb = d_adj + (size_t)b*NN*NN;
  #pragma unroll
  for (int mt = 0; mt < 2; mt++){
    #pragma unroll
    for (int nt = 0; nt < 8; nt++){
      int i1 = mo + mt*16 + g, i2 = i1 + 8;
      int j0 = no + nt*8 + t*2, j1 = j0 + 1;
      if (j0 < NN){
        if (i1 < NN) adjb[(size_t)i1*NN + j0] = (unsigned char)((acc[mt][nt][0] > 0.6f) || (i1 == j0));
        if (i2 < NN) adjb[(size_t)i2*NN + j0] = (unsigned char)((acc[mt][nt][2] > 0.6f) || (i2 == j0));
      }
      if (j1 < NN){
        if (i1 < NN) adjb[(size_t)i1*NN + j1] = (unsigned char)((acc[mt][nt][1] > 0.6f) || (i1 == j1));
        if (i2 < NN) adjb[(size_t)i2*NN + j1] = (unsigned char)((acc[mt][nt][3] > 0.6f) || (i2 == j1));
      }
    }
  }
}

// ---------------- 7a) GAT: h = f @ W, plus attention coefficient terms ----------------
__global__ __launch_bounds__(64) void gat_h(int layer, const float* __restrict__ W,
    const float* __restrict__ aw_src, const float* __restrict__ aw_dst){
  __shared__ float sh[4];
  int bi = blockIdx.x;                 // 0..815 node
  int o = threadIdx.x;                 // 0..63 output
  int in_dim = layer ? NGD : NC;
  const float* f = (layer ? d_g0 : d_feats) + (size_t)bi * in_dim;
  float s = 0.f;
  for (int c = 0; c < in_dim; c += 4){
    float f0 = f[c], f1 = f[c+1], f2 = f[c+2], f3 = f[c+3];
    s += f0*W[(c  )*NGD+o];
    s += f1*W[(c+1)*NGD+o];
    s += f2*W[(c+2)*NGD+o];
    s += f3*W[(c+3)*NGD+o];
  }
  d_h[(size_t)bi*NGD + o] = s;
  float vs = wsum(s * aw_src[o]);
  float vd = wsum(s * aw_dst[o]);
  if ((o & 31) == 0){ sh[o>>5] = vs; sh[2 + (o>>5)] = vd; }
  __syncthreads();
  if (o == 0){ d_asrc[bi] = sh[0] + sh[1]; d_adst[bi] = sh[2] + sh[3]; }
}

// ---------------- 7b) GAT: softmax over neighbors + aggregate + relu ----------------
__global__ __launch_bounds__(128) void gat_agg(int layer, const float* __restrict__ bias){
  __shared__ float alpha[NN];
  __shared__ float red[4];
  __shared__ float part[128];
  int bi = blockIdx.x; int b = bi / NN;
  int tid = threadIdx.x;
  const unsigned char* arow = d_adj + (size_t)bi * NN;  // adj symmetric -> mask.T == mask
  float ad = d_adst[bi];
  float sum = 0.f;
  for (int j = tid; j < NN; j += 128){
    float lg = ad + d_asrc[b*NN + j];
    lg = lg > 0.f ? lg : 0.2f*lg;
    float e = arow[j] ? __expf(lg) : 0.f;
    alpha[j] = e;
    sum += e;
  }
  sum = wsum(sum);
  if ((tid & 31) == 0) red[tid>>5] = sum;
  __syncthreads();                       // also makes alpha writes visible
  float inv = 1.f / (red[0] + red[1] + red[2] + red[3]);
  int o = tid & 63, half = tid >> 6;
  float acc = 0.f;
  for (int j = half*51; j < half*51 + 51; j++)
    acc += alpha[j] * d_h[((size_t)b*NN + j)*NGD + o];
  part[tid] = acc;
  __syncthreads();
  if (tid < 64){
    float r = (part[tid] + part[tid + 64]) * inv + bias[tid];
    (layer ? d_g1 : d_g0)[(size_t)bi*NGD + tid] = fmaxf(r, 0.f);
  }
}

// ---------------- 8) graph -> attention gates + dense per-(b,h,hw) scatter ----------------
__global__ __launch_bounds__(256) void g2a_kernel(const float* __restrict__ wg,
                                                  const float* __restrict__ bg){
  __shared__ float sg[NN*NHEAD];
  int b = blockIdx.x, tid = threadIdx.x;
  for (int idx = tid; idx < NN*NHEAD; idx += 256){
    int i = idx >> 3, hh = idx & 7;
    const float* gr = d_g1 + ((size_t)b*NN + i) * NGD;
    float s = bg[hh];
    #pragma unroll
    for (int o = 0; o < NGD; o++) s += gr[o] * wg[hh*NGD + o];
    sg[idx] = 1.f / (1.f + __expf(-s));
  }
  __syncthreads();
  for (int hw = tid; hw < NHW; hw += 256){
    int node = d_nodeof[b*NHW + hw];
    #pragma unroll
    for (int h = 0; h < NHEAD; h++){
      float g = (node >= 0) ? sg[node*NHEAD + h] : 0.f;
      d_gh[((size_t)(b*NHEAD + h))*NHW + hw] = g;
    }
  }
}

// ---------------- 9) QKV GEMM via tf32 mma (scale folded into Q) ----------------
__global__ __launch_bounds__(256) void qkv_mma(const float* __restrict__ Wq){
  __shared__ unsigned As[128*20];
  __shared__ unsigned Bs[128*20];
  int tid = threadIdx.x, w = tid>>5, lane = tid&31;
  int g = lane>>2, t = lane&3;
  int mo = (w>>1)*32, no = (w&1)*64;
  int rowBase = blockIdx.y*128, colBase = blockIdx.x*128;
  float acc[2][8][4];
  #pragma unroll
  for (int mt=0;mt<2;mt++)
    #pragma unroll
    for (int nt=0;nt<8;nt++)
      #pragma unroll
      for (int r=0;r<4;r++) acc[mt][nt][r] = 0.f;

  for (int k0 = 0; k0 < 256; k0 += 16){
    __syncthreads();
    #pragma unroll
    for (int l = 0; l < 2; l++){
      int idx = tid + l*256;
      int r = idx>>2, c4 = (idx&3)<<2;
      float4 va = *(const float4*)&d_xs[(size_t)(rowBase + r)*256 + k0 + c4];
      *(uint4*)&As[r*20 + c4] = cvt4(va);
      float4 vb = *(const float4*)&Wq[(size_t)(colBase + r)*256 + k0 + c4];
      *(uint4*)&Bs[r*20 + c4] = cvt4(vb);
    }
    __syncthreads();
    #pragma unroll
    for (int kc = 0; kc < 2; kc++){
      unsigned a[2][4];
      #pragma unroll
      for (int mt = 0; mt < 2; mt++){
        int r = mo + mt*16;
        a[mt][0] = As[(r+g  )*20 + kc*8 + t];
        a[mt][1] = As[(r+g+8)*20 + kc*8 + t];
        a[mt][2] = As[(r+g  )*20 + kc*8 + t + 4];
        a[mt][3] = As[(r+g+8)*20 + kc*8 + t + 4];
      }
      #pragma unroll
      for (int nt = 0; nt < 8; nt++){
        unsigned b0 = Bs[(no + nt*8 + g)*20 + kc*8 + t];
        unsigned b1 = Bs[(no + nt*8 + g)*20 + kc*8 + t + 4];
        mma_tf32(acc[0][nt], a[0], b0, b1);
        mma_tf32(acc[1][nt], a[1], b0, b1);
      }
    }
  }
  #pragma unroll
  for (int mt = 0; mt < 2; mt++){
    #pragma unroll
    for (int nt = 0; nt < 8; nt++){
      int col = colBase + no + nt*8 + t*2;
      int sct = col >> 8, hh = (col >> 5) & 7, dd = col & 31;
      float* base = (sct == 0) ? d_q : (sct == 1 ? d_k : d_v);
      float sc = (sct == 0) ? 0.17677669529663687f : 1.f;   // fold 1/sqrt(32) into Q
      int m1 = rowBase + mo + mt*16 + g;
      int b1 = m1 >> 10, hw1 = m1 & 1023;
      *(float2*)&base[(((size_t)(b1*8 + hh))*1024 + hw1)*32 + dd] =
          make_float2(acc[mt][nt][0]*sc, acc[mt][nt][1]*sc);
      int m2 = m1 + 8;
      int b2 = m2 >> 10, hw2 = m2 & 1023;
      *(float2*)&base[(((size_t)(b2*8 + hh))*1024 + hw2)*32 + dd] =
          make_float2(acc[mt][nt][2]*sc, acc[mt][nt][3]*sc);
    }
  }
}

// ---------------- 10) fused flash attention + graph modulation (tf32 mma) ----------------
// Scores are bounded (|s| < ~2): fixed-max softmax, no online rescaling.
#define KSS 36
#define VSS 40
__global__ __launch_bounds__(256) void attn_mma(){
  __shared__ unsigned Ks[64*KSS];
  __shared__ unsigned Vs[64*VSS];
  __shared__ float kg[64]; __shared__ int kn[64];
  __shared__ float qg[128]; __shared__ int qn[128];

  int bh = blockIdx.x, b = bh>>3, h = bh&7;
  int q0 = blockIdx.y << 7;        // 128 q rows per block
  int tid = threadIdx.x, w = tid>>5, lane = tid&31;
  int g = lane>>2, t = lane&3;

  // Q fragments (scale already folded in by qkv_mma)
  unsigned aQ[4][4];
  {
    const float* Qb = d_q + ((size_t)bh*NHW + q0 + w*16)*NHD;
    #pragma unroll
    for (int kc = 0; kc < 4; kc++){
      aQ[kc][0] = f2tf32(Qb[(g  )*NHD + kc*8 + t    ]);
      aQ[kc][1] = f2tf32(Qb[(g+8)*NHD + kc*8 + t    ]);
      aQ[kc][2] = f2tf32(Qb[(g  )*NHD + kc*8 + t + 4]);
      aQ[kc][3] = f2tf32(Qb[(g+8)*NHD + kc*8 + t + 4]);
    }
  }
  if (tid < 128){
    qn[tid] = d_nodeof[b*NHW + q0 + tid];
    qg[tid] = d_gh[(size_t)bh*NHW + q0 + tid];
  }

  const unsigned char* adjb = d_adj + (size_t)b * NN * NN;
  int r1 = w*16 + g, r2 = r1 + 8;

  float l1 = 0.f, l2 = 0.f;
  float o[4][4];
  #pragma unroll
  for (int dt = 0; dt < 4; dt++)
    #pragma unroll
    for (int r = 0; r < 4; r++) o[dt][r] = 0.f;

  for (int kt = 0; kt < 16; kt++){
    __syncthreads();
    const float* Kb = d_k + ((size_t)bh*NHW + kt*64)*NHD;
    const float* Vb = d_v + ((size_t)bh*NHW + kt*64)*NHD;
    #pragma unroll
    for (int l = 0; l < 2; l++){
      int idx = tid + l*256;
      int r = idx>>3, c4 = (idx&7)<<2;
      float4 kv = *(const float4*)(Kb + r*NHD + c4);
      *(uint4*)&Ks[r*KSS + c4] = cvt4(kv);
      float4 vv = *(const float4*)(Vb + r*NHD + c4);
      *(uint4*)&Vs[r*VSS + c4] = cvt4(vv);
    }
    if (tid < 64){
      kn[tid] = d_nodeof[b*NHW + kt*64 + tid];
      kg[tid] = d_gh[(size_t)bh*NHW + kt*64 + tid];
    }
    __syncthreads();

    // S = Q K^T : per-warp 16x64 via 4 kchunks x 8 ntiles
    float s[8][4];
    #pragma unroll
    for (int nt = 0; nt < 8; nt++)
      #pragma unroll
      for (int r = 0; r < 4; r++) s[nt][r] = 0.f;
    #pragma unroll
    for (int kc = 0; kc < 4; kc++){
      #pragma unroll
      for (int nt = 0; nt < 8; nt++){
        unsigned b0 = Ks[(nt*8 + g)*KSS + kc*8 + t];
        unsigned b1 = Ks[(nt*8 + g)*KSS + kc*8 + t + 4];
        mma_tf32(s[nt], aQ[kc], b0, b1);
      }
    }

    // graph modulation
    int iq1 = qn[r1], iq2 = qn[r2];
    if (iq1 >= 0 || iq2 >= 0){
      float qg1 = qg[r1], qg2 = qg[r2];
      #pragma unroll
      for (int nt = 0; nt < 8; nt++){
        int c = nt*8 + t*2;
        int k0 = kn[c], k1 = kn[c+1];
        if (iq1 >= 0){
          if (k0 >= 0 && adjb[iq1*NN + k0]) s[nt][0] += qg1 * kg[c];
          if (k1 >= 0 && adjb[iq1*NN + k1]) s[nt][1] += qg1 * kg[c+1];
        }
        if (iq2 >= 0){
          if (k0 >= 0 && adjb[iq2*NN + k0]) s[nt][2] += qg2 * kg[c];
          if (k1 >= 0 && adjb[iq2*NN + k1]) s[nt][3] += qg2 * kg[c+1];
        }
      }
    }

    // fixed-max softmax: exp directly, accumulate row sums
    float sm1 = 0.f, sm2 = 0.f;
    #pragma unroll
    for (int nt = 0; nt < 8; nt++){
      s[nt][0] = __expf(s[nt][0]); sm1 += s[nt][0];
      s[nt][1] = __expf(s[nt][1]); sm1 += s[nt][1];
      s[nt][2] = __expf(s[nt][2]); sm2 += s[nt][2];
      s[nt][3] = __expf(s[nt][3]); sm2 += s[nt][3];
    }
    sm1 += __shfl_xor_sync(0xffffffffu, sm1, 1);
    sm1 += __shfl_xor_sync(0xffffffffu, sm1, 2);
    sm2 += __shfl_xor_sync(0xffffffffu, sm2, 1);
    sm2 += __shfl_xor_sync(0xffffffffu, sm2, 2);
    l1 += sm1; l2 += sm2;

    // O += P V : re-layout P (C-frag) -> A-frag via shuffles, then mma
    int srcA = (lane & ~3) | (t >> 1);
    int srcB = srcA + 2;
    bool odd = (t & 1);
    #pragma unroll
    for (int kc = 0; kc < 8; kc++){
      float q00 = __shfl_sync(0xffffffffu, s[kc][0], srcA);
      float q01 = __shfl_sync(0xffffffffu, s[kc][1], srcA);
      float q20 = __shfl_sync(0xffffffffu, s[kc][2], srcA);
      float q21 = __shfl_sync(0xffffffffu, s[kc][3], srcA);
      float u00 = __shfl_sync(0xffffffffu, s[kc][0], srcB);
      float u01 = __shfl_sync(0xffffffffu, s[kc][1], srcB);
      float u20 = __shfl_sync(0xffffffffu, s[kc][2], srcB);
      float u21 = __shfl_sync(0xffffffffu, s[kc][3], srcB);
      unsigned aP[4];
      aP[0] = f2tf32(odd ? q01 : q00);
      aP[1] = f2tf32(odd ? q21 : q20);
      aP[2] = f2tf32(odd ? u01 : u00);
      aP[3] = f2tf32(odd ? u21 : u20);
      #pragma unroll
      for (int dt = 0; dt < 4; dt++){
        unsigned b0 = Vs[(kc*8 + t    )*VSS + dt*8 + g];
        unsigned b1 = Vs[(kc*8 + t + 4)*VSS + dt*8 + g];
        mma_tf32(o[dt], aP, b0, b1);
      }
    }
  }

  // epilogue
  float i1 = 1.f / l1, i2 = 1.f / l2;
  float* dst1 = d_ao + ((size_t)b*NHW + q0 + r1)*NC + h*NHD;
  float* dst2 = dst1 + 8*NC;
  #pragma unroll
  for (int dt = 0; dt < 4; dt++){
    int col = dt*8 + t*2;
    *(float2*)&dst1[col] = make_float2(o[dt][0]*i1, o[dt][1]*i1);
    *(float2*)&dst2[col] = make_float2(o[dt][2]*i2, o[dt][3]*i2);
  }
}

// ---------------- 11) proj GEMM (operands swapped: M=channel, N=hw) ----------------
__global__ __launch_bounds__(256) void proj_mma(const float* __restrict__ Wp,
    const float* __restrict__ bias, float* __restrict__ out){
  __shared__ unsigned As[128*20];     // Wp rows (c)
  __shared__ unsigned Bs[128*20];     // ao rows (hw)
  int tid = threadIdx.x, w = tid>>5, lane = tid&31;
  int g = lane>>2, t = lane&3;
  int mo = (w>>1)*32, no = (w&1)*64;
  int cBase = blockIdx.x*128, hwBase = blockIdx.y*128;
  float acc[2][8][4];
  #pragma unroll
  for (int mt=0;mt<2;mt++)
    #pragma unroll
    for (int nt=0;nt<8;nt++)
      #pragma unroll
      for (int r=0;r<4;r++) acc[mt][nt][r] = 0.f;

  for (int k0 = 0; k0 < 256; k0 += 16){
    __syncthreads();
    #pragma unroll
    for (int l = 0; l < 2; l++){
      int idx = tid + l*256;
      int r = idx>>2, c4 = (idx&3)<<2;
      float4 va = *(const float4*)&Wp[(size_t)(cBase + r)*256 + k0 + c4];
      *(uint4*)&As[r*20 + c4] = cvt4(va);
      float4 vb = *(const float4*)&d_ao[(size_t)(hwBase + r)*256 + k0 + c4];
      *(uint4*)&Bs[r*20 + c4] = cvt4(vb);
    }
    __syncthreads();
    #pragma unroll
    for (int kc = 0; kc < 2; kc++){
      unsigned a[2][4];
      #pragma unroll
      for (int mt = 0; mt < 2; mt++){
        int r = mo + mt*16;
        a[mt][0] = As[(r+g  )*20 + kc*8 + t];
        a[mt][1] = As[(r+g+8)*20 + kc*8 + t];
        a[mt][2] = As[(r+g  )*20 + kc*8 + t + 4];
        a[mt][3] = As[(r+g+8)*20 + kc*8 + t + 4];
      }
      #pragma unroll
      for (int nt = 0; nt < 8; nt++){
        unsigned b0 = Bs[(no + nt*8 + g)*20 + kc*8 + t];
        unsigned b1 = Bs[(no + nt*8 + g)*20 + kc*8 + t + 4];
        mma_tf32(acc[0][nt], a[0], b0, b1);
        mma_tf32(acc[1][nt], a[1], b0, b1);
      }
    }
  }
  #pragma unroll
  for (int mt = 0; mt < 2; mt++){
    #pragma unroll
    for (int nt = 0; nt < 8; nt++){
      int c1 = cBase + mo + mt*16 + g;
      int c2 = c1 + 8;
      int hw = hwBase + no + nt*8 + t*2;
      int b = hw >> 10, hwl = hw & 1023;
      float bc1 = bias[c1], bc2 = bias[c2];
      *(float2*)&out[((size_t)(b*NC + c1))*NHW + hwl] =
          make_float2(acc[mt][nt][0] + bc1, acc[mt][nt][1] + bc1);
      *(float2*)&out[((size_t)(b*NC + c2))*NHW + hwl] =
          make_float2(acc[mt][nt][2] + bc2, acc[mt][nt][3] + bc2);
    }
  }
}

// ---------------- launch ----------------
extern "C" void kernel_launch(void* const* d_in, const int* in_sizes, int n_in,
                              void* d_out, int out_size){
  (void)in_sizes; (void)n_in; (void)out_size;
  const float* x      = (const float*)d_in[0];
  const float* w_qkv  = (const float*)d_in[1];
  const float* w_proj = (const float*)d_in[2];
  const float* b_proj = (const float*)d_in[3];
  const float* g0W    = (const float*)d_in[4];
  const float* g0s    = (const float*)d_in[5];
  const float* g0d    = (const float*)d_in[6];
  const float* g0b    = (const float*)d_in[7];
  const float* g1W    = (const float*)d_in[8];
  const float* g1s    = (const float*)d_in[9];
  const float* g1d    = (const float*)d_in[10];
  const float* g1b    = (const float*)d_in[11];
  const float* wg2a   = (const float*)d_in[12];
  const float* bg2a   = (const float*)d_in[13];
  float* out = (float*)d_out;

  static cudaStream_t side = nullptr;
  static cudaEvent_t evFork = nullptr, evJoin = nullptr;
  if (!side){
    cudaStreamCreateWithFlags(&side, cudaStreamNonBlocking);
    cudaEventCreateWithFlags(&evFork, cudaEventDisableTiming);
    cudaEventCreateWithFlags(&evJoin, cudaEventDisableTiming);
  }

  transpose_kernel<<<dim3(32, 8, 8), dim3(32, 8)>>>(x);

  // fork: graph-side chain on side stream, QKV on main stream
  cudaEventRecord(evFork, 0);
  cudaStreamWaitEvent(side, evFork, 0);

  imptopk_kernel<<<8, 1024, 0, side>>>();
  adj_mma<<<8, 256, 0, side>>>();
  gat_h<<<816, 64, 0, side>>>(0, g0W, g0s, g0d);
  gat_agg<<<816, 128, 0, side>>>(0, g0b);
  gat_h<<<816, 64, 0, side>>>(1, g1W, g1s, g1d);
  gat_agg<<<816, 128, 0, side>>>(1, g1b);
  g2a_kernel<<<8, 256, 0, side>>>(wg2a, bg2a);
  cudaEventRecord(evJoin, side);

  qkv_mma<<<dim3(6, 64), 256>>>(w_qkv);

  cudaStreamWaitEvent(0, evJoin, 0);
  attn_mma<<<dim3(64, 8), 256>>>();
  proj_mma<<<dim3(2, 64), 256>>>(w_proj, b_proj, out);
}